// round 1
// baseline (speedup 1.0000x reference)
#include <cuda_runtime.h>
#include <cuda_bf16.h>

// Problem dims (fixed by reference)
#define HWDIM 196
#define BATCH 64
#define DDIM  768
#define EDIM  256
#define CDIM  10
#define M1    (BATCH * HWDIM)   // 12544 rows (b,h)

// Scratch (static device globals — no allocation anywhere)
__device__ float g_S[(size_t)M1 * EDIM];            // sign pattern, 12.8 MB
__device__ float g_T[(size_t)BATCH * EDIM * DDIM];  // T[b,e,d] = sum_h s*x, 50.3 MB
__device__ float g_P[(size_t)EDIM * BATCH * CDIM];  // per-e partial preds, 0.66 MB

// ---------------------------------------------------------------------------
// Kernel 1: S = (X @ ag_w^T + ag_b) > 0   (M=12544, N=256, K=768, fp32 exact)
// grid (4, 98), block 256. Tile 128(M) x 64(N), micro 8x4, BK=16.
// ---------------------------------------------------------------------------
__global__ __launch_bounds__(256) void k1_sign_gemm(
    const float* __restrict__ X, const float* __restrict__ W,
    const float* __restrict__ bias)
{
    const int BM = 128, BN = 64, BK = 16;
    __shared__ float Xs[BK][BM + 4];
    __shared__ float Ws[BK][BN + 4];

    const int tid = threadIdx.x;
    const int tx = tid & 15;   // N direction (4 cols each)
    const int ty = tid >> 4;   // M direction (8 rows each)
    const int m0 = blockIdx.y * BM;
    const int n0 = blockIdx.x * BN;

    float acc[8][4];
    #pragma unroll
    for (int i = 0; i < 8; i++)
        #pragma unroll
        for (int j = 0; j < 4; j++) acc[i][j] = 0.f;

    for (int k0 = 0; k0 < DDIM; k0 += BK) {
        // X tile 128x16 -> Xs[k][m] (transposed store)
        #pragma unroll
        for (int l = 0; l < 2; l++) {
            int s   = tid + l * 256;        // 0..511 float4 slots
            int row = s >> 2;               // 0..127
            int c4  = (s & 3) * 4;          // 0,4,8,12
            float4 v = *reinterpret_cast<const float4*>(
                &X[(size_t)(m0 + row) * DDIM + k0 + c4]);
            Xs[c4 + 0][row] = v.x;
            Xs[c4 + 1][row] = v.y;
            Xs[c4 + 2][row] = v.z;
            Xs[c4 + 3][row] = v.w;
        }
        // W tile 64x16 -> Ws[k][n]
        {
            int row = tid >> 2;             // 0..63
            int c4  = (tid & 3) * 4;
            float4 v = *reinterpret_cast<const float4*>(
                &W[(size_t)(n0 + row) * DDIM + k0 + c4]);
            Ws[c4 + 0][row] = v.x;
            Ws[c4 + 1][row] = v.y;
            Ws[c4 + 2][row] = v.z;
            Ws[c4 + 3][row] = v.w;
        }
        __syncthreads();

        #pragma unroll
        for (int kk = 0; kk < BK; kk++) {
            float ra[8], rb[4];
            #pragma unroll
            for (int i = 0; i < 8; i++) ra[i] = Xs[kk][ty * 8 + i];
            #pragma unroll
            for (int j = 0; j < 4; j++) rb[j] = Ws[kk][tx * 4 + j];
            #pragma unroll
            for (int i = 0; i < 8; i++)
                #pragma unroll
                for (int j = 0; j < 4; j++) acc[i][j] += ra[i] * rb[j];
        }
        __syncthreads();
    }

    #pragma unroll
    for (int j = 0; j < 4; j++) {
        int n = n0 + tx * 4 + j;
        float b = bias[n];
        #pragma unroll
        for (int i = 0; i < 8; i++) {
            int m = m0 + ty * 8 + i;
            g_S[(size_t)m * EDIM + n] = (acc[i][j] + b > 0.f) ? 1.f : 0.f;
        }
    }
}

// ---------------------------------------------------------------------------
// Kernel 2: per batch b, T[b] = S[b]^T @ X[b]  (M=256 e, N=768 d, K=196 h)
// grid (6, 4, 64), block 256. Tile 64(e) x 128(d), micro 4x8, BK=16 (ragged K).
// ---------------------------------------------------------------------------
__global__ __launch_bounds__(256) void k2_maskT(const float* __restrict__ X)
{
    const int BM = 64, BN = 128, BK = 16;
    __shared__ float Ss[BK][BM + 4];
    __shared__ float Xs[BK][BN + 4];

    const int tid = threadIdx.x;
    const int tx = tid & 15;   // d direction (8 each)
    const int ty = tid >> 4;   // e direction (4 each)
    const int b  = blockIdx.z;
    const int e0 = blockIdx.y * BM;
    const int d0 = blockIdx.x * BN;

    float acc[4][8];
    #pragma unroll
    for (int i = 0; i < 4; i++)
        #pragma unroll
        for (int j = 0; j < 8; j++) acc[i][j] = 0.f;

    for (int k0 = 0; k0 < HWDIM; k0 += BK) {
        // S tile 16h x 64e -> Ss[h][e]  (natural layout, no transpose)
        {
            int h  = tid >> 4;            // 0..15
            int e4 = (tid & 15) * 4;
            int hh = k0 + h;
            float4 v = make_float4(0.f, 0.f, 0.f, 0.f);
            if (hh < HWDIM)
                v = *reinterpret_cast<const float4*>(
                    &g_S[(size_t)(b * HWDIM + hh) * EDIM + e0 + e4]);
            *reinterpret_cast<float4*>(&Ss[h][e4]) = v;
        }
        // X tile 16h x 128d -> Xs[h][d]
        #pragma unroll
        for (int l = 0; l < 2; l++) {
            int s  = tid + l * 256;       // 0..511
            int h  = s >> 5;              // 0..15
            int d4 = (s & 31) * 4;
            int hh = k0 + h;
            float4 v = make_float4(0.f, 0.f, 0.f, 0.f);
            if (hh < HWDIM)
                v = *reinterpret_cast<const float4*>(
                    &X[(size_t)(b * HWDIM + hh) * DDIM + d0 + d4]);
            *reinterpret_cast<float4*>(&Xs[h][d4]) = v;
        }
        __syncthreads();

        #pragma unroll
        for (int kk = 0; kk < BK; kk++) {
            float ra[4], rb[8];
            #pragma unroll
            for (int i = 0; i < 4; i++) ra[i] = Ss[kk][ty * 4 + i];
            #pragma unroll
            for (int j = 0; j < 8; j++) rb[j] = Xs[kk][tx * 8 + j];
            #pragma unroll
            for (int i = 0; i < 4; i++)
                #pragma unroll
                for (int j = 0; j < 8; j++) acc[i][j] += ra[i] * rb[j];
        }
        __syncthreads();
    }

    #pragma unroll
    for (int i = 0; i < 4; i++) {
        size_t row = (size_t)(b * EDIM + e0 + ty * 4 + i) * DDIM + d0 + tx * 8;
        float4 v0 = make_float4(acc[i][0], acc[i][1], acc[i][2], acc[i][3]);
        float4 v1 = make_float4(acc[i][4], acc[i][5], acc[i][6], acc[i][7]);
        *reinterpret_cast<float4*>(&g_T[row + 0]) = v0;
        *reinterpret_cast<float4*>(&g_T[row + 4]) = v1;
    }
}

// ---------------------------------------------------------------------------
// Kernel 3: per e, P[e][b,c] = sum_d T[b,e,d] * lm_w[e*C+c, d]
// grid 256 (e), block 320 (each thread owns 2 (b,c) pairs).
// ---------------------------------------------------------------------------
__global__ __launch_bounds__(320) void k3_contract(const float* __restrict__ LW)
{
    __shared__ float Tds[64][132];
    __shared__ float Wds[10][132];

    const int tid = threadIdx.x;
    const int e   = blockIdx.x;
    const int p0  = tid;         // 0..319
    const int p1  = tid + 320;   // 320..639
    const int b0_ = p0 / 10, c0_ = p0 % 10;
    const int b1_ = p1 / 10, c1_ = p1 % 10;

    float acc0 = 0.f, acc1 = 0.f;

    for (int d0 = 0; d0 < DDIM; d0 += 128) {
        // T chunk: 64 b x 128 d (2048 float4 slots)
        for (int s = tid; s < 2048; s += 320) {
            int bb = s >> 5;
            int d4 = (s & 31) * 4;
            *reinterpret_cast<float4*>(&Tds[bb][d4]) =
                *reinterpret_cast<const float4*>(
                    &g_T[(size_t)(bb * EDIM + e) * DDIM + d0 + d4]);
        }
        // W chunk: 10 c x 128 d (320 float4 slots)
        {
            int cc = tid >> 5;    // 0..9
            int d4 = (tid & 31) * 4;
            *reinterpret_cast<float4*>(&Wds[cc][d4]) =
                *reinterpret_cast<const float4*>(
                    &LW[(size_t)(e * CDIM + cc) * DDIM + d0 + d4]);
        }
        __syncthreads();

        #pragma unroll 4
        for (int d = 0; d < 128; d++) {
            acc0 += Tds[b0_][d] * Wds[c0_][d];
            acc1 += Tds[b1_][d] * Wds[c1_][d];
        }
        __syncthreads();
    }

    g_P[(size_t)e * (BATCH * CDIM) + p0] = acc0;
    g_P[(size_t)e * (BATCH * CDIM) + p1] = acc1;
}

// ---------------------------------------------------------------------------
// Kernel 4: out[b,c] = (1/(HW*E)) * sum_e P[e][b,c]
// ---------------------------------------------------------------------------
__global__ void k4_reduce(float* __restrict__ out)
{
    int p = blockIdx.x * blockDim.x + threadIdx.x;
    if (p < BATCH * CDIM) {
        float s = 0.f;
        for (int e = 0; e < EDIM; e++)
            s += g_P[(size_t)e * (BATCH * CDIM) + p];
        out[p] = s * (1.0f / ((float)HWDIM * (float)EDIM));
    }
}

// ---------------------------------------------------------------------------
extern "C" void kernel_launch(void* const* d_in, const int* in_sizes, int n_in,
                              void* d_out, int out_size)
{
    const float* X   = (const float*)d_in[0];   // (64,196,768)
    const float* AGW = (const float*)d_in[1];   // (256,768)
    const float* AGB = (const float*)d_in[2];   // (256,)
    const float* LW  = (const float*)d_in[3];   // (2560,768)
    float* out = (float*)d_out;                 // (64,10)

    k1_sign_gemm<<<dim3(EDIM / 64, M1 / 128), 256>>>(X, AGW, AGB);
    k2_maskT<<<dim3(DDIM / 128, EDIM / 64, BATCH), 256>>>(X);
    k3_contract<<<EDIM, 320>>>(LW);
    k4_reduce<<<3, 256>>>(out);
}

// round 2
// speedup vs baseline: 1.2673x; 1.2673x over previous
#include <cuda_runtime.h>
#include <cuda_bf16.h>

// Problem dims (fixed by reference)
#define HWDIM 196
#define BATCH 64
#define DDIM  768
#define EDIM  256
#define CDIM  10
#define M1    (BATCH * HWDIM)   // 12544 rows (b,h)

// Scratch (static device globals — no allocation anywhere)
__device__ float g_S[(size_t)M1 * EDIM];            // sign pattern, 12.8 MB
__device__ float g_T[(size_t)BATCH * EDIM * DDIM];  // T[b,e,d], 50.3 MB

// ---------------------------------------------------------------------------
// Kernel 1: S = (X @ ag_w^T + ag_b) > 0   (M=12544, N=256, K=768, fp32 exact)
// Tile 128(M) x 64(N), 128 threads, micro 8x8, BK=16, double-buffered smem.
// grid (4, 98).
// ---------------------------------------------------------------------------
__global__ __launch_bounds__(128) void k1_sign_gemm(
    const float* __restrict__ X, const float* __restrict__ W,
    const float* __restrict__ bias)
{
    __shared__ float Xs[2][16][128 + 4];
    __shared__ float Ws[2][16][64 + 4];

    const int tid = threadIdx.x;
    const int tx  = tid & 7;      // N dir, 8 cols each
    const int ty  = tid >> 3;     // M dir, 8 rows each
    const int m0  = blockIdx.y * 128;
    const int n0  = blockIdx.x * 64;

    const int grow = tid >> 2;         // 0..31
    const int gc4  = (tid & 3) * 4;    // 0,4,8,12

    float4 xa[4], wa[2];

    // prologue: load tile 0
    #pragma unroll
    for (int l = 0; l < 4; l++)
        xa[l] = *reinterpret_cast<const float4*>(
            &X[(size_t)(m0 + grow + l * 32) * DDIM + gc4]);
    #pragma unroll
    for (int l = 0; l < 2; l++)
        wa[l] = *reinterpret_cast<const float4*>(
            &W[(size_t)(n0 + grow + l * 32) * DDIM + gc4]);

    #pragma unroll
    for (int l = 0; l < 4; l++) {
        Xs[0][gc4 + 0][grow + l * 32] = xa[l].x;
        Xs[0][gc4 + 1][grow + l * 32] = xa[l].y;
        Xs[0][gc4 + 2][grow + l * 32] = xa[l].z;
        Xs[0][gc4 + 3][grow + l * 32] = xa[l].w;
    }
    #pragma unroll
    for (int l = 0; l < 2; l++) {
        Ws[0][gc4 + 0][grow + l * 32] = wa[l].x;
        Ws[0][gc4 + 1][grow + l * 32] = wa[l].y;
        Ws[0][gc4 + 2][grow + l * 32] = wa[l].z;
        Ws[0][gc4 + 3][grow + l * 32] = wa[l].w;
    }
    __syncthreads();

    float acc[8][8];
    #pragma unroll
    for (int i = 0; i < 8; i++)
        #pragma unroll
        for (int j = 0; j < 8; j++) acc[i][j] = 0.f;

    int buf = 0;
    const int NT = DDIM / 16;   // 48
    for (int t = 0; t < NT; t++) {
        if (t < NT - 1) {
            int k0 = (t + 1) * 16;
            #pragma unroll
            for (int l = 0; l < 4; l++)
                xa[l] = *reinterpret_cast<const float4*>(
                    &X[(size_t)(m0 + grow + l * 32) * DDIM + k0 + gc4]);
            #pragma unroll
            for (int l = 0; l < 2; l++)
                wa[l] = *reinterpret_cast<const float4*>(
                    &W[(size_t)(n0 + grow + l * 32) * DDIM + k0 + gc4]);
        }

        #pragma unroll
        for (int kk = 0; kk < 16; kk++) {
            float ra[8], rb[8];
            *reinterpret_cast<float4*>(&ra[0]) =
                *reinterpret_cast<const float4*>(&Xs[buf][kk][ty * 8 + 0]);
            *reinterpret_cast<float4*>(&ra[4]) =
                *reinterpret_cast<const float4*>(&Xs[buf][kk][ty * 8 + 4]);
            *reinterpret_cast<float4*>(&rb[0]) =
                *reinterpret_cast<const float4*>(&Ws[buf][kk][tx * 8 + 0]);
            *reinterpret_cast<float4*>(&rb[4]) =
                *reinterpret_cast<const float4*>(&Ws[buf][kk][tx * 8 + 4]);
            #pragma unroll
            for (int i = 0; i < 8; i++)
                #pragma unroll
                for (int j = 0; j < 8; j++) acc[i][j] += ra[i] * rb[j];
        }

        if (t < NT - 1) {
            int nb = buf ^ 1;
            #pragma unroll
            for (int l = 0; l < 4; l++) {
                Xs[nb][gc4 + 0][grow + l * 32] = xa[l].x;
                Xs[nb][gc4 + 1][grow + l * 32] = xa[l].y;
                Xs[nb][gc4 + 2][grow + l * 32] = xa[l].z;
                Xs[nb][gc4 + 3][grow + l * 32] = xa[l].w;
            }
            #pragma unroll
            for (int l = 0; l < 2; l++) {
                Ws[nb][gc4 + 0][grow + l * 32] = wa[l].x;
                Ws[nb][gc4 + 1][grow + l * 32] = wa[l].y;
                Ws[nb][gc4 + 2][grow + l * 32] = wa[l].z;
                Ws[nb][gc4 + 3][grow + l * 32] = wa[l].w;
            }
        }
        buf ^= 1;
        __syncthreads();
    }

    // epilogue: bias + sign -> g_S
    float bv[8];
    #pragma unroll
    for (int j = 0; j < 8; j++) bv[j] = bias[n0 + tx * 8 + j];

    #pragma unroll
    for (int i = 0; i < 8; i++) {
        int m = m0 + ty * 8 + i;
        float4 o0, o1;
        o0.x = (acc[i][0] + bv[0] > 0.f) ? 1.f : 0.f;
        o0.y = (acc[i][1] + bv[1] > 0.f) ? 1.f : 0.f;
        o0.z = (acc[i][2] + bv[2] > 0.f) ? 1.f : 0.f;
        o0.w = (acc[i][3] + bv[3] > 0.f) ? 1.f : 0.f;
        o1.x = (acc[i][4] + bv[4] > 0.f) ? 1.f : 0.f;
        o1.y = (acc[i][5] + bv[5] > 0.f) ? 1.f : 0.f;
        o1.z = (acc[i][6] + bv[6] > 0.f) ? 1.f : 0.f;
        o1.w = (acc[i][7] + bv[7] > 0.f) ? 1.f : 0.f;
        *reinterpret_cast<float4*>(&g_S[(size_t)m * EDIM + n0 + tx * 8 + 0]) = o0;
        *reinterpret_cast<float4*>(&g_S[(size_t)m * EDIM + n0 + tx * 8 + 4]) = o1;
    }
}

// ---------------------------------------------------------------------------
// Kernel 2: per batch b, T[b] = S[b]^T @ X[b]  (M=256 e, N=768 d, K=196 h)
// Tile 128(e) x 64(d), 128 threads, micro 8x8, BK=16 (13 ragged tiles),
// double-buffered. grid (12, 2, 64).
// ---------------------------------------------------------------------------
__global__ __launch_bounds__(128) void k2_maskT(const float* __restrict__ X)
{
    __shared__ float Ss[2][16][128 + 4];
    __shared__ float Xs[2][16][64 + 4];

    const int tid = threadIdx.x;
    const int tx  = tid & 7;     // d dir
    const int ty  = tid >> 3;    // e dir
    const int b   = blockIdx.z;
    const int e0  = blockIdx.y * 128;
    const int d0  = blockIdx.x * 64;

    // A = S[b]: k-major already (row h, col e): 16x128 = 512 float4
    const int ah  = tid >> 5;          // +l*4, l=0..3
    const int ae4 = (tid & 31) * 4;
    // B = X[b]: row h, col d: 16x64 = 256 float4
    const int bh  = tid >> 4;          // +l*8, l=0..1
    const int bd4 = (tid & 15) * 4;

    const float* Sb = &g_S[(size_t)b * HWDIM * EDIM];
    const float* Xb = &X[(size_t)b * HWDIM * DDIM];

    float4 sa[4], xb[2];

    auto load_tile = [&](int k0) {
        #pragma unroll
        for (int l = 0; l < 4; l++) {
            int hh = k0 + ah + l * 4;
            sa[l] = (hh < HWDIM)
                ? *reinterpret_cast<const float4*>(&Sb[(size_t)hh * EDIM + e0 + ae4])
                : make_float4(0.f, 0.f, 0.f, 0.f);
        }
        #pragma unroll
        for (int l = 0; l < 2; l++) {
            int hh = k0 + bh + l * 8;
            xb[l] = (hh < HWDIM)
                ? *reinterpret_cast<const float4*>(&Xb[(size_t)hh * DDIM + d0 + bd4])
                : make_float4(0.f, 0.f, 0.f, 0.f);
        }
    };
    auto store_tile = [&](int nb) {
        #pragma unroll
        for (int l = 0; l < 4; l++)
            *reinterpret_cast<float4*>(&Ss[nb][ah + l * 4][ae4]) = sa[l];
        #pragma unroll
        for (int l = 0; l < 2; l++)
            *reinterpret_cast<float4*>(&Xs[nb][bh + l * 8][bd4]) = xb[l];
    };

    load_tile(0);
    store_tile(0);
    __syncthreads();

    float acc[8][8];
    #pragma unroll
    for (int i = 0; i < 8; i++)
        #pragma unroll
        for (int j = 0; j < 8; j++) acc[i][j] = 0.f;

    int buf = 0;
    const int NT = (HWDIM + 15) / 16;   // 13
    for (int t = 0; t < NT; t++) {
        if (t < NT - 1) load_tile((t + 1) * 16);

        #pragma unroll
        for (int kk = 0; kk < 16; kk++) {
            float ra[8], rb[8];
            *reinterpret_cast<float4*>(&ra[0]) =
                *reinterpret_cast<const float4*>(&Ss[buf][kk][ty * 8 + 0]);
            *reinterpret_cast<float4*>(&ra[4]) =
                *reinterpret_cast<const float4*>(&Ss[buf][kk][ty * 8 + 4]);
            *reinterpret_cast<float4*>(&rb[0]) =
                *reinterpret_cast<const float4*>(&Xs[buf][kk][tx * 8 + 0]);
            *reinterpret_cast<float4*>(&rb[4]) =
                *reinterpret_cast<const float4*>(&Xs[buf][kk][tx * 8 + 4]);
            #pragma unroll
            for (int i = 0; i < 8; i++)
                #pragma unroll
                for (int j = 0; j < 8; j++) acc[i][j] += ra[i] * rb[j];
        }

        if (t < NT - 1) store_tile(buf ^ 1);
        buf ^= 1;
        __syncthreads();
    }

    #pragma unroll
    for (int i = 0; i < 8; i++) {
        size_t row = (size_t)(b * EDIM + e0 + ty * 8 + i) * DDIM + d0 + tx * 8;
        float4 v0 = make_float4(acc[i][0], acc[i][1], acc[i][2], acc[i][3]);
        float4 v1 = make_float4(acc[i][4], acc[i][5], acc[i][6], acc[i][7]);
        *reinterpret_cast<float4*>(&g_T[row + 0]) = v0;
        *reinterpret_cast<float4*>(&g_T[row + 4]) = v1;
    }
}

// ---------------------------------------------------------------------------
// Kernel 3a: zero the output (harness poisons it).
// ---------------------------------------------------------------------------
__global__ void k3_zero(float* __restrict__ out)
{
    int p = blockIdx.x * blockDim.x + threadIdx.x;
    if (p < BATCH * CDIM) out[p] = 0.f;
}

// ---------------------------------------------------------------------------
// Kernel 3: per (e, d-half), partial[b,c] = sum_d T[b,e,d]*lm_w[e*C+c,d];
// atomicAdd scaled partials into out. grid (256, 2), block 320.
// ---------------------------------------------------------------------------
__global__ __launch_bounds__(320) void k3_contract(
    const float* __restrict__ LW, float* __restrict__ out)
{
    __shared__ float Tds[64][132];
    __shared__ float Wds[10][132];

    const int tid = threadIdx.x;
    const int e   = blockIdx.x;
    const int dbase = blockIdx.y * 384;
    const int p0  = tid;         // 0..319
    const int p1  = tid + 320;   // 320..639
    const int b0_ = p0 / 10, c0_ = p0 % 10;
    const int b1_ = p1 / 10, c1_ = p1 % 10;

    float acc0 = 0.f, acc1 = 0.f;

    for (int c = 0; c < 3; c++) {
        int d0 = dbase + c * 128;
        // T chunk: 64 b x 128 d
        for (int s = tid; s < 2048; s += 320) {
            int bb = s >> 5;
            int d4 = (s & 31) * 4;
            *reinterpret_cast<float4*>(&Tds[bb][d4]) =
                *reinterpret_cast<const float4*>(
                    &g_T[(size_t)(bb * EDIM + e) * DDIM + d0 + d4]);
        }
        // W chunk: 10 c x 128 d
        {
            int cc = tid >> 5;    // 0..9
            int d4 = (tid & 31) * 4;
            *reinterpret_cast<float4*>(&Wds[cc][d4]) =
                *reinterpret_cast<const float4*>(
                    &LW[(size_t)(e * CDIM + cc) * DDIM + d0 + d4]);
        }
        __syncthreads();

        #pragma unroll 4
        for (int d = 0; d < 128; d++) {
            acc0 += Tds[b0_][d] * Wds[c0_][d];
            acc1 += Tds[b1_][d] * Wds[c1_][d];
        }
        __syncthreads();
    }

    const float scale = 1.0f / ((float)HWDIM * (float)EDIM);
    atomicAdd(&out[p0], acc0 * scale);
    atomicAdd(&out[p1], acc1 * scale);
}

// ---------------------------------------------------------------------------
extern "C" void kernel_launch(void* const* d_in, const int* in_sizes, int n_in,
                              void* d_out, int out_size)
{
    const float* X   = (const float*)d_in[0];   // (64,196,768)
    const float* AGW = (const float*)d_in[1];   // (256,768)
    const float* AGB = (const float*)d_in[2];   // (256,)
    const float* LW  = (const float*)d_in[3];   // (2560,768)
    float* out = (float*)d_out;                 // (64,10)

    k1_sign_gemm<<<dim3(EDIM / 64, M1 / 128), 128>>>(X, AGW, AGB);
    k2_maskT<<<dim3(DDIM / 64, EDIM / 128, BATCH), 128>>>(X);
    k3_zero<<<3, 256>>>(out);
    k3_contract<<<dim3(EDIM, 2), 320>>>(LW, out);
}

// round 4
// speedup vs baseline: 1.3363x; 1.0544x over previous
#include <cuda_runtime.h>
#include <cuda_bf16.h>

// Problem dims (fixed by reference)
#define HWDIM 196
#define BATCH 64
#define DDIM  768
#define EDIM  256
#define CDIM  10
#define M1    (BATCH * HWDIM)   // 12544 rows (b,h)

typedef unsigned long long ull;

// Packed dual-fp32 FMA: acc.{lo,hi} += a.{lo,hi} * b.{lo,hi}
#define FMA2(acc, a, b) \
    asm("fma.rn.f32x2 %0, %1, %2, %0;" : "+l"(acc) : "l"(a), "l"(b))
#define PACK2(p, v) \
    asm("mov.b64 %0, {%1, %1};" : "=l"(p) : "f"(v))
#define UNPACK2(lo, hi, p) \
    asm("mov.b64 {%0, %1}, %2;" : "=f"(lo), "=f"(hi) : "l"(p))

// Scratch (static device globals — no allocation anywhere)
__device__ float g_S[(size_t)M1 * EDIM];            // sign pattern, 12.8 MB
__device__ float g_T[(size_t)BATCH * EDIM * DDIM];  // T[b,e,d], 50.3 MB

// ---------------------------------------------------------------------------
// Kernel 1: S = (X @ ag_w^T + ag_b) > 0   (M=12544, N=256, K=768, fp32 exact)
// Tile 128(M) x 64(N), 128 threads, micro 8x8 via f32x2 (4 M-pairs x 8 N),
// BK=16, double-buffered smem. grid (4, 98).
// ---------------------------------------------------------------------------
__global__ __launch_bounds__(128) void k1_sign_gemm(
    const float* __restrict__ X, const float* __restrict__ W,
    const float* __restrict__ bias)
{
    __shared__ float Xs[2][16][128 + 4];
    __shared__ float Ws[2][16][64 + 4];

    const int tid = threadIdx.x;
    const int tx  = tid & 7;      // N dir, 8 cols each
    const int ty  = tid >> 3;     // M dir, 8 rows each
    const int m0  = blockIdx.y * 128;
    const int n0  = blockIdx.x * 64;

    const int grow = tid >> 2;         // 0..31
    const int gc4  = (tid & 3) * 4;    // 0,4,8,12

    float4 xa[4], wa[2];

    #pragma unroll
    for (int l = 0; l < 4; l++)
        xa[l] = *reinterpret_cast<const float4*>(
            &X[(size_t)(m0 + grow + l * 32) * DDIM + gc4]);
    #pragma unroll
    for (int l = 0; l < 2; l++)
        wa[l] = *reinterpret_cast<const float4*>(
            &W[(size_t)(n0 + grow + l * 32) * DDIM + gc4]);

    #pragma unroll
    for (int l = 0; l < 4; l++) {
        Xs[0][gc4 + 0][grow + l * 32] = xa[l].x;
        Xs[0][gc4 + 1][grow + l * 32] = xa[l].y;
        Xs[0][gc4 + 2][grow + l * 32] = xa[l].z;
        Xs[0][gc4 + 3][grow + l * 32] = xa[l].w;
    }
    #pragma unroll
    for (int l = 0; l < 2; l++) {
        Ws[0][gc4 + 0][grow + l * 32] = wa[l].x;
        Ws[0][gc4 + 1][grow + l * 32] = wa[l].y;
        Ws[0][gc4 + 2][grow + l * 32] = wa[l].z;
        Ws[0][gc4 + 3][grow + l * 32] = wa[l].w;
    }
    __syncthreads();

    ull acc2[4][8];
    #pragma unroll
    for (int i = 0; i < 4; i++)
        #pragma unroll
        for (int j = 0; j < 8; j++) acc2[i][j] = 0ull;

    int buf = 0;
    const int NT = DDIM / 16;   // 48
    for (int t = 0; t < NT; t++) {
        if (t < NT - 1) {
            int k0 = (t + 1) * 16;
            #pragma unroll
            for (int l = 0; l < 4; l++)
                xa[l] = *reinterpret_cast<const float4*>(
                    &X[(size_t)(m0 + grow + l * 32) * DDIM + k0 + gc4]);
            #pragma unroll
            for (int l = 0; l < 2; l++)
                wa[l] = *reinterpret_cast<const float4*>(
                    &W[(size_t)(n0 + grow + l * 32) * DDIM + k0 + gc4]);
        }

        #pragma unroll
        for (int kk = 0; kk < 16; kk++) {
            // A fragment: 8 M-rows as 4 packed pairs (memory-adjacent pairs)
            ulonglong2 a01 = *reinterpret_cast<const ulonglong2*>(&Xs[buf][kk][ty * 8 + 0]);
            ulonglong2 a23 = *reinterpret_cast<const ulonglong2*>(&Xs[buf][kk][ty * 8 + 4]);
            ull ra2[4] = { a01.x, a01.y, a23.x, a23.y };
            // B fragment: 8 N-cols, each duplicated into both lanes
            float rbv[8];
            *reinterpret_cast<float4*>(&rbv[0]) =
                *reinterpret_cast<const float4*>(&Ws[buf][kk][tx * 8 + 0]);
            *reinterpret_cast<float4*>(&rbv[4]) =
                *reinterpret_cast<const float4*>(&Ws[buf][kk][tx * 8 + 4]);
            ull rb2[8];
            #pragma unroll
            for (int j = 0; j < 8; j++) PACK2(rb2[j], rbv[j]);
            #pragma unroll
            for (int i = 0; i < 4; i++)
                #pragma unroll
                for (int j = 0; j < 8; j++) FMA2(acc2[i][j], ra2[i], rb2[j]);
        }

        if (t < NT - 1) {
            int nb = buf ^ 1;
            #pragma unroll
            for (int l = 0; l < 4; l++) {
                Xs[nb][gc4 + 0][grow + l * 32] = xa[l].x;
                Xs[nb][gc4 + 1][grow + l * 32] = xa[l].y;
                Xs[nb][gc4 + 2][grow + l * 32] = xa[l].z;
                Xs[nb][gc4 + 3][grow + l * 32] = xa[l].w;
            }
            #pragma unroll
            for (int l = 0; l < 2; l++) {
                Ws[nb][gc4 + 0][grow + l * 32] = wa[l].x;
                Ws[nb][gc4 + 1][grow + l * 32] = wa[l].y;
                Ws[nb][gc4 + 2][grow + l * 32] = wa[l].z;
                Ws[nb][gc4 + 3][grow + l * 32] = wa[l].w;
            }
        }
        buf ^= 1;
        __syncthreads();
    }

    // unpack accumulators: accf[row 0..7][col 0..7]
    float accf[8][8];
    #pragma unroll
    for (int i = 0; i < 4; i++)
        #pragma unroll
        for (int j = 0; j < 8; j++)
            UNPACK2(accf[2 * i][j], accf[2 * i + 1][j], acc2[i][j]);

    float bv[8];
    #pragma unroll
    for (int j = 0; j < 8; j++) bv[j] = bias[n0 + tx * 8 + j];

    #pragma unroll
    for (int i = 0; i < 8; i++) {
        int m = m0 + ty * 8 + i;
        float4 o0, o1;
        o0.x = (accf[i][0] + bv[0] > 0.f) ? 1.f : 0.f;
        o0.y = (accf[i][1] + bv[1] > 0.f) ? 1.f : 0.f;
        o0.z = (accf[i][2] + bv[2] > 0.f) ? 1.f : 0.f;
        o0.w = (accf[i][3] + bv[3] > 0.f) ? 1.f : 0.f;
        o1.x = (accf[i][4] + bv[4] > 0.f) ? 1.f : 0.f;
        o1.y = (accf[i][5] + bv[5] > 0.f) ? 1.f : 0.f;
        o1.z = (accf[i][6] + bv[6] > 0.f) ? 1.f : 0.f;
        o1.w = (accf[i][7] + bv[7] > 0.f) ? 1.f : 0.f;
        *reinterpret_cast<float4*>(&g_S[(size_t)m * EDIM + n0 + tx * 8 + 0]) = o0;
        *reinterpret_cast<float4*>(&g_S[(size_t)m * EDIM + n0 + tx * 8 + 4]) = o1;
    }
}

// ---------------------------------------------------------------------------
// Kernel 2: per batch b, T[b] = S[b]^T @ X[b]  (M=256 e, N=768 d, K=196 h)
// Tile 128(e) x 64(d), 128 threads, micro 8x8 via f32x2, BK=16 (13 ragged),
// double-buffered. grid (12, 2, 64).
// ---------------------------------------------------------------------------
__global__ __launch_bounds__(128) void k2_maskT(const float* __restrict__ X)
{
    __shared__ float Ss[2][16][128 + 4];
    __shared__ float Xs[2][16][64 + 4];

    const int tid = threadIdx.x;
    const int tx  = tid & 7;     // d dir
    const int ty  = tid >> 3;    // e dir
    const int b   = blockIdx.z;
    const int e0  = blockIdx.y * 128;
    const int d0  = blockIdx.x * 64;

    const int ah  = tid >> 5;          // +l*4, l=0..3
    const int ae4 = (tid & 31) * 4;
    const int bh  = tid >> 4;          // +l*8, l=0..1
    const int bd4 = (tid & 15) * 4;

    const float* Sb = &g_S[(size_t)b * HWDIM * EDIM];
    const float* Xb = &X[(size_t)b * HWDIM * DDIM];

    float4 sa[4], xb[2];

    auto load_tile = [&](int k0) {
        #pragma unroll
        for (int l = 0; l < 4; l++) {
            int hh = k0 + ah + l * 4;
            sa[l] = (hh < HWDIM)
                ? *reinterpret_cast<const float4*>(&Sb[(size_t)hh * EDIM + e0 + ae4])
                : make_float4(0.f, 0.f, 0.f, 0.f);
        }
        #pragma unroll
        for (int l = 0; l < 2; l++) {
            int hh = k0 + bh + l * 8;
            xb[l] = (hh < HWDIM)
                ? *reinterpret_cast<const float4*>(&Xb[(size_t)hh * DDIM + d0 + bd4])
                : make_float4(0.f, 0.f, 0.f, 0.f);
        }
    };
    auto store_tile = [&](int nb) {
        #pragma unroll
        for (int l = 0; l < 4; l++)
            *reinterpret_cast<float4*>(&Ss[nb][ah + l * 4][ae4]) = sa[l];
        #pragma unroll
        for (int l = 0; l < 2; l++)
            *reinterpret_cast<float4*>(&Xs[nb][bh + l * 8][bd4]) = xb[l];
    };

    load_tile(0);
    store_tile(0);
    __syncthreads();

    ull acc2[4][8];
    #pragma unroll
    for (int i = 0; i < 4; i++)
        #pragma unroll
        for (int j = 0; j < 8; j++) acc2[i][j] = 0ull;

    int buf = 0;
    const int NT = (HWDIM + 15) / 16;   // 13
    for (int t = 0; t < NT; t++) {
        if (t < NT - 1) load_tile((t + 1) * 16);

        #pragma unroll
        for (int kk = 0; kk < 16; kk++) {
            ulonglong2 a01 = *reinterpret_cast<const ulonglong2*>(&Ss[buf][kk][ty * 8 + 0]);
            ulonglong2 a23 = *reinterpret_cast<const ulonglong2*>(&Ss[buf][kk][ty * 8 + 4]);
            ull ra2[4] = { a01.x, a01.y, a23.x, a23.y };
            float rbv[8];
            *reinterpret_cast<float4*>(&rbv[0]) =
                *reinterpret_cast<const float4*>(&Xs[buf][kk][tx * 8 + 0]);
            *reinterpret_cast<float4*>(&rbv[4]) =
                *reinterpret_cast<const float4*>(&Xs[buf][kk][tx * 8 + 4]);
            ull rb2[8];
            #pragma unroll
            for (int j = 0; j < 8; j++) PACK2(rb2[j], rbv[j]);
            #pragma unroll
            for (int i = 0; i < 4; i++)
                #pragma unroll
                for (int j = 0; j < 8; j++) FMA2(acc2[i][j], ra2[i], rb2[j]);
        }

        if (t < NT - 1) store_tile(buf ^ 1);
        buf ^= 1;
        __syncthreads();
    }

    float accf[8][8];
    #pragma unroll
    for (int i = 0; i < 4; i++)
        #pragma unroll
        for (int j = 0; j < 8; j++)
            UNPACK2(accf[2 * i][j], accf[2 * i + 1][j], acc2[i][j]);

    #pragma unroll
    for (int i = 0; i < 8; i++) {
        size_t row = (size_t)(b * EDIM + e0 + ty * 8 + i) * DDIM + d0 + tx * 8;
        float4 v0 = make_float4(accf[i][0], accf[i][1], accf[i][2], accf[i][3]);
        float4 v1 = make_float4(accf[i][4], accf[i][5], accf[i][6], accf[i][7]);
        *reinterpret_cast<float4*>(&g_T[row + 0]) = v0;
        *reinterpret_cast<float4*>(&g_T[row + 4]) = v1;
    }
}

// ---------------------------------------------------------------------------
// Kernel 3a: zero the output (harness poisons it).
// ---------------------------------------------------------------------------
__global__ void k3_zero(float* __restrict__ out)
{
    int p = blockIdx.x * blockDim.x + threadIdx.x;
    if (p < BATCH * CDIM) out[p] = 0.f;
}

// ---------------------------------------------------------------------------
// Kernel 3: per (e, d-third): partial[b,c] = sum_d T[b,e,d]*lm_w[e*C+c,d];
// float4 LDS inner loop (4x fewer LDS instr). grid (256, 3), block 320.
// ---------------------------------------------------------------------------
__global__ __launch_bounds__(320) void k3_contract(
    const float* __restrict__ LW, float* __restrict__ out)
{
    __shared__ float Tds[64][132];
    __shared__ float Wds[10][132];

    const int tid = threadIdx.x;
    const int e   = blockIdx.x;
    const int dbase = blockIdx.y * 256;
    const int p0  = tid;         // 0..319
    const int p1  = tid + 320;   // 320..639
    const int b0_ = p0 / 10, c0_ = p0 % 10;
    const int b1_ = p1 / 10, c1_ = p1 % 10;

    float4 acc0 = make_float4(0.f, 0.f, 0.f, 0.f);
    float4 acc1 = make_float4(0.f, 0.f, 0.f, 0.f);

    #pragma unroll
    for (int c = 0; c < 2; c++) {
        int d0 = dbase + c * 128;
        // T chunk: 64 b x 128 d
        for (int s = tid; s < 2048; s += 320) {
            int bb = s >> 5;
            int d4 = (s & 31) * 4;
            *reinterpret_cast<float4*>(&Tds[bb][d4]) =
                *reinterpret_cast<const float4*>(
                    &g_T[(size_t)(bb * EDIM + e) * DDIM + d0 + d4]);
        }
        // W chunk: 10 c x 128 d
        {
            int cc = tid >> 5;    // 0..9
            int d4 = (tid & 31) * 4;
            *reinterpret_cast<float4*>(&Wds[cc][d4]) =
                *reinterpret_cast<const float4*>(
                    &LW[(size_t)(e * CDIM + cc) * DDIM + d0 + d4]);
        }
        __syncthreads();

        #pragma unroll 4
        for (int i = 0; i < 32; i++) {
            float4 t0 = *reinterpret_cast<const float4*>(&Tds[b0_][i * 4]);
            float4 w0 = *reinterpret_cast<const float4*>(&Wds[c0_][i * 4]);
            float4 t1 = *reinterpret_cast<const float4*>(&Tds[b1_][i * 4]);
            float4 w1 = *reinterpret_cast<const float4*>(&Wds[c1_][i * 4]);
            acc0.x += t0.x * w0.x;  acc0.y += t0.y * w0.y;
            acc0.z += t0.z * w0.z;  acc0.w += t0.w * w0.w;
            acc1.x += t1.x * w1.x;  acc1.y += t1.y * w1.y;
            acc1.z += t1.z * w1.z;  acc1.w += t1.w * w1.w;
        }
        __syncthreads();
    }

    const float scale = 1.0f / ((float)HWDIM * (float)EDIM);
    atomicAdd(&out[p0], (acc0.x + acc0.y + acc0.z + acc0.w) * scale);
    atomicAdd(&out[p1], (acc1.x + acc1.y + acc1.z + acc1.w) * scale);
}

// ---------------------------------------------------------------------------
extern "C" void kernel_launch(void* const* d_in, const int* in_sizes, int n_in,
                              void* d_out, int out_size)
{
    const float* X   = (const float*)d_in[0];   // (64,196,768)
    const float* AGW = (const float*)d_in[1];   // (256,768)
    const float* AGB = (const float*)d_in[2];   // (256,)
    const float* LW  = (const float*)d_in[3];   // (2560,768)
    float* out = (float*)d_out;                 // (64,10)

    k1_sign_gemm<<<dim3(EDIM / 64, M1 / 128), 128>>>(X, AGW, AGB);
    k2_maskT<<<dim3(DDIM / 64, EDIM / 128, BATCH), 128>>>(X);
    k3_zero<<<3, 256>>>(out);
    k3_contract<<<dim3(EDIM, 3), 320>>>(LW, out);
}

// round 6
// speedup vs baseline: 1.3614x; 1.0188x over previous
#include <cuda_runtime.h>
#include <cuda_bf16.h>

// Problem dims (fixed by reference)
#define HWDIM 196
#define BATCH 64
#define DDIM  768
#define EDIM  256
#define CDIM  10
#define M1    (BATCH * HWDIM)   // 12544 rows (b,h)

typedef unsigned long long ull;

// Packed dual-fp32 FMA: acc.{lo,hi} += a.{lo,hi} * b.{lo,hi}
#define FMA2(acc, a, b) \
    asm("fma.rn.f32x2 %0, %1, %2, %0;" : "+l"(acc) : "l"(a), "l"(b))
#define PACK2(p, v) \
    asm("mov.b64 %0, {%1, %1};" : "=l"(p) : "f"(v))
#define UNPACK2(lo, hi, p) \
    asm("mov.b64 {%0, %1}, %2;" : "=f"(lo), "=f"(hi) : "l"(p))

__device__ __forceinline__ void cp16(void* smem_dst, const void* gsrc) {
    unsigned sa = (unsigned)__cvta_generic_to_shared(smem_dst);
    asm volatile("cp.async.cg.shared.global [%0], [%1], 16;" :: "r"(sa), "l"(gsrc));
}
#define CP_COMMIT() asm volatile("cp.async.commit_group;")
#define CP_WAIT0()  asm volatile("cp.async.wait_group 0;")

// Scratch (static device globals — no allocation anywhere)
__device__ float g_S[(size_t)M1 * EDIM];            // sign pattern, 12.8 MB
__device__ float g_T[(size_t)BATCH * EDIM * DDIM];  // T[b,e,d], 50.3 MB

// ---------------------------------------------------------------------------
// Kernel 1: S = (X @ ag_w^T + ag_b) > 0   (M=12544, N=256, K=768, fp32 exact)
// Tile 256(M) x 32(N), 128 threads, micro 16Mx4N via f32x2 (8 M-pairs x 4 N),
// BK=16, double-buffered smem (register staging; transpose on store).
// grid (8, 49).
// ---------------------------------------------------------------------------
__global__ __launch_bounds__(128) void k1_sign_gemm(
    const float* __restrict__ X, const float* __restrict__ W,
    const float* __restrict__ bias)
{
    __shared__ float Xs[2][16][260];
    __shared__ float Ws[2][16][36];

    const int tid = threadIdx.x;
    const int tx  = tid & 7;      // N dir: 4 cols each
    const int ty  = tid >> 3;     // M dir: 16 rows each (0..15)
    const int m0  = blockIdx.y * 256;
    const int n0  = blockIdx.x * 32;

    const int ar  = tid >> 2;          // 0..31, rows ar + 32l
    const int ac4 = (tid & 3) * 4;     // k sub-offset

    float4 xa[8], wa;

    auto gload = [&](int k0) {
        #pragma unroll
        for (int l = 0; l < 8; l++)
            xa[l] = *reinterpret_cast<const float4*>(
                &X[(size_t)(m0 + ar + l * 32) * DDIM + k0 + ac4]);
        wa = *reinterpret_cast<const float4*>(
            &W[(size_t)(n0 + ar) * DDIM + k0 + ac4]);
    };
    auto sstore = [&](int nb) {
        #pragma unroll
        for (int l = 0; l < 8; l++) {
            Xs[nb][ac4 + 0][ar + l * 32] = xa[l].x;
            Xs[nb][ac4 + 1][ar + l * 32] = xa[l].y;
            Xs[nb][ac4 + 2][ar + l * 32] = xa[l].z;
            Xs[nb][ac4 + 3][ar + l * 32] = xa[l].w;
        }
        Ws[nb][ac4 + 0][ar] = wa.x;
        Ws[nb][ac4 + 1][ar] = wa.y;
        Ws[nb][ac4 + 2][ar] = wa.z;
        Ws[nb][ac4 + 3][ar] = wa.w;
    };

    gload(0);
    sstore(0);
    __syncthreads();

    ull acc2[8][4];
    #pragma unroll
    for (int i = 0; i < 8; i++)
        #pragma unroll
        for (int j = 0; j < 4; j++) acc2[i][j] = 0ull;

    int buf = 0;
    const int NT = DDIM / 16;   // 48
    for (int t = 0; t < NT; t++) {
        if (t < NT - 1) gload((t + 1) * 16);

        #pragma unroll
        for (int kk = 0; kk < 16; kk++) {
            ull ra2[8];
            #pragma unroll
            for (int u = 0; u < 4; u++) {
                ulonglong2 a = *reinterpret_cast<const ulonglong2*>(
                    &Xs[buf][kk][ty * 16 + u * 4]);
                ra2[2 * u + 0] = a.x;
                ra2[2 * u + 1] = a.y;
            }
            float4 wb = *reinterpret_cast<const float4*>(&Ws[buf][kk][tx * 4]);
            ull rb2[4];
            PACK2(rb2[0], wb.x);
            PACK2(rb2[1], wb.y);
            PACK2(rb2[2], wb.z);
            PACK2(rb2[3], wb.w);
            #pragma unroll
            for (int i = 0; i < 8; i++)
                #pragma unroll
                for (int j = 0; j < 4; j++) FMA2(acc2[i][j], ra2[i], rb2[j]);
        }

        if (t < NT - 1) sstore(buf ^ 1);
        buf ^= 1;
        __syncthreads();
    }

    float accf[16][4];
    #pragma unroll
    for (int p = 0; p < 8; p++)
        #pragma unroll
        for (int j = 0; j < 4; j++)
            UNPACK2(accf[2 * p][j], accf[2 * p + 1][j], acc2[p][j]);

    float bv[4];
    #pragma unroll
    for (int j = 0; j < 4; j++) bv[j] = bias[n0 + tx * 4 + j];

    #pragma unroll
    for (int r = 0; r < 16; r++) {
        int m = m0 + ty * 16 + r;
        float4 o;
        o.x = (accf[r][0] + bv[0] > 0.f) ? 1.f : 0.f;
        o.y = (accf[r][1] + bv[1] > 0.f) ? 1.f : 0.f;
        o.z = (accf[r][2] + bv[2] > 0.f) ? 1.f : 0.f;
        o.w = (accf[r][3] + bv[3] > 0.f) ? 1.f : 0.f;
        *reinterpret_cast<float4*>(&g_S[(size_t)m * EDIM + n0 + tx * 4]) = o;
    }
}

// ---------------------------------------------------------------------------
// Kernel 2: per batch b, T[b] = S[b]^T @ X[b]  (M=256 e, N=768 d, K=196 h)
// Tile 256(e) x 64(d), 128 threads, micro 16x8 via f32x2, BK=16 (13 ragged),
// cp.async double-buffered (both tiles are direct copies). grid (12, 64).
// ---------------------------------------------------------------------------
__global__ __launch_bounds__(128) void k2_maskT(const float* __restrict__ X)
{
    __shared__ float Ss[2][16][260];
    __shared__ float Xs2[2][16][68];

    const int tid = threadIdx.x;
    const int tx  = tid & 7;     // d dir: 8 each
    const int ty  = tid >> 3;    // e dir: 16 each
    const int b   = blockIdx.y;
    const int d0  = blockIdx.x * 64;

    const float* Sb = &g_S[(size_t)b * HWDIM * EDIM];
    const float* Xb = &X[(size_t)b * HWDIM * DDIM];

    // A tile (S): 16h x 256e = 1024 float4, 8/thread
    // B tile (X): 16h x 64d  = 256 float4, 2/thread
    auto issue = [&](int k0, int nb) {
        #pragma unroll
        for (int l = 0; l < 8; l++) {
            int s  = tid + l * 128;
            int h  = s >> 6;
            int e4 = (s & 63) * 4;
            int hh = k0 + h;
            if (hh < HWDIM)
                cp16(&Ss[nb][h][e4], &Sb[(size_t)hh * EDIM + e4]);
            else
                *reinterpret_cast<float4*>(&Ss[nb][h][e4]) =
                    make_float4(0.f, 0.f, 0.f, 0.f);
        }
        #pragma unroll
        for (int l = 0; l < 2; l++) {
            int s  = tid + l * 128;
            int h  = s >> 4;
            int d4 = (s & 15) * 4;
            int hh = k0 + h;
            if (hh < HWDIM)
                cp16(&Xs2[nb][h][d4], &Xb[(size_t)hh * DDIM + d0 + d4]);
            else
                *reinterpret_cast<float4*>(&Xs2[nb][h][d4]) =
                    make_float4(0.f, 0.f, 0.f, 0.f);
        }
        CP_COMMIT();
    };

    issue(0, 0);

    ull acc2[8][8];
    #pragma unroll
    for (int i = 0; i < 8; i++)
        #pragma unroll
        for (int j = 0; j < 8; j++) acc2[i][j] = 0ull;

    int buf = 0;
    const int NT = (HWDIM + 15) / 16;   // 13
    for (int t = 0; t < NT; t++) {
        CP_WAIT0();
        __syncthreads();
        if (t < NT - 1) issue((t + 1) * 16, buf ^ 1);

        #pragma unroll
        for (int kk = 0; kk < 16; kk++) {
            ull ra2[8];
            #pragma unroll
            for (int u = 0; u < 4; u++) {
                ulonglong2 a = *reinterpret_cast<const ulonglong2*>(
                    &Ss[buf][kk][ty * 16 + u * 4]);
                ra2[2 * u + 0] = a.x;
                ra2[2 * u + 1] = a.y;
            }
            float rbv[8];
            *reinterpret_cast<float4*>(&rbv[0]) =
                *reinterpret_cast<const float4*>(&Xs2[buf][kk][tx * 8 + 0]);
            *reinterpret_cast<float4*>(&rbv[4]) =
                *reinterpret_cast<const float4*>(&Xs2[buf][kk][tx * 8 + 4]);
            ull rb2[8];
            #pragma unroll
            for (int j = 0; j < 8; j++) PACK2(rb2[j], rbv[j]);
            #pragma unroll
            for (int i = 0; i < 8; i++)
                #pragma unroll
                for (int j = 0; j < 8; j++) FMA2(acc2[i][j], ra2[i], rb2[j]);
        }
        buf ^= 1;
    }

    float accf[16][8];
    #pragma unroll
    for (int p = 0; p < 8; p++)
        #pragma unroll
        for (int j = 0; j < 8; j++)
            UNPACK2(accf[2 * p][j], accf[2 * p + 1][j], acc2[p][j]);

    #pragma unroll
    for (int r = 0; r < 16; r++) {
        size_t row = (size_t)(b * EDIM + ty * 16 + r) * DDIM + d0 + tx * 8;
        float4 v0 = make_float4(accf[r][0], accf[r][1], accf[r][2], accf[r][3]);
        float4 v1 = make_float4(accf[r][4], accf[r][5], accf[r][6], accf[r][7]);
        *reinterpret_cast<float4*>(&g_T[row + 0]) = v0;
        *reinterpret_cast<float4*>(&g_T[row + 4]) = v1;
    }
}

// ---------------------------------------------------------------------------
// Kernel 3a: zero the output (harness poisons it).
// ---------------------------------------------------------------------------
__global__ void k3_zero(float* __restrict__ out)
{
    int p = blockIdx.x * blockDim.x + threadIdx.x;
    if (p < BATCH * CDIM) out[p] = 0.f;
}

// ---------------------------------------------------------------------------
// Kernel 3: one block per e. out[b,c] += sum_d T[b,e,d]*lm_w[e*C+c,d].
// Thread tile 4b x 10c, both operands packed over d (f32x2, no PACK movs).
// Block 256 = 16 bg x 16 dl. Shuffle-reduce over dl, atomicAdd to out.
// ---------------------------------------------------------------------------
__global__ __launch_bounds__(256) void k3_contract(
    const float* __restrict__ LW, float* __restrict__ out)
{
    __shared__ float Tds[64][132];
    __shared__ float Wds[10][132];

    const int tid = threadIdx.x;
    const int e   = blockIdx.x;
    const int dl  = tid & 15;     // d-lane
    const int bg  = tid >> 4;     // 0..15 -> b rows bg*4..+3

    ull acc2[4][10];
    #pragma unroll
    for (int i = 0; i < 4; i++)
        #pragma unroll
        for (int c = 0; c < 10; c++) acc2[i][c] = 0ull;

    for (int d0 = 0; d0 < DDIM; d0 += 128) {
        // stage T: 64b x 128d (2048 float4, 8/thread)
        #pragma unroll
        for (int l = 0; l < 8; l++) {
            int s  = tid + l * 256;
            int bb = s >> 5;
            int d4 = (s & 31) * 4;
            *reinterpret_cast<float4*>(&Tds[bb][d4]) =
                *reinterpret_cast<const float4*>(
                    &g_T[(size_t)(bb * EDIM + e) * DDIM + d0 + d4]);
        }
        // stage W: 10c x 128d (320 float4) -- strided over 256 threads (BUGFIX)
        for (int s = tid; s < 320; s += 256) {
            int cc = s >> 5;
            int d4 = (s & 31) * 4;
            *reinterpret_cast<float4*>(&Wds[cc][d4]) =
                *reinterpret_cast<const float4*>(
                    &LW[(size_t)(e * CDIM + cc) * DDIM + d0 + d4]);
        }
        __syncthreads();

        #pragma unroll
        for (int j = 0; j < 4; j++) {
            int pp = dl + 16 * j;      // d-pair index 0..63
            ull tp[4], wp[10];
            #pragma unroll
            for (int i = 0; i < 4; i++)
                tp[i] = *reinterpret_cast<const ull*>(&Tds[bg * 4 + i][2 * pp]);
            #pragma unroll
            for (int c = 0; c < 10; c++)
                wp[c] = *reinterpret_cast<const ull*>(&Wds[c][2 * pp]);
            #pragma unroll
            for (int i = 0; i < 4; i++)
                #pragma unroll
                for (int c = 0; c < 10; c++) FMA2(acc2[i][c], tp[i], wp[c]);
        }
        __syncthreads();
    }

    const float scale = 1.0f / ((float)HWDIM * (float)EDIM);
    #pragma unroll
    for (int i = 0; i < 4; i++) {
        #pragma unroll
        for (int c = 0; c < 10; c++) {
            float lo, hi;
            UNPACK2(lo, hi, acc2[i][c]);
            float v = lo + hi;
            v += __shfl_xor_sync(0xFFFFFFFFu, v, 1);
            v += __shfl_xor_sync(0xFFFFFFFFu, v, 2);
            v += __shfl_xor_sync(0xFFFFFFFFu, v, 4);
            v += __shfl_xor_sync(0xFFFFFFFFu, v, 8);
            if (dl == 0)
                atomicAdd(&out[(bg * 4 + i) * CDIM + c], v * scale);
        }
    }
}

// ---------------------------------------------------------------------------
extern "C" void kernel_launch(void* const* d_in, const int* in_sizes, int n_in,
                              void* d_out, int out_size)
{
    const float* X   = (const float*)d_in[0];   // (64,196,768)
    const float* AGW = (const float*)d_in[1];   // (256,768)
    const float* AGB = (const float*)d_in[2];   // (256,)
    const float* LW  = (const float*)d_in[3];   // (2560,768)
    float* out = (float*)d_out;                 // (64,10)

    k1_sign_gemm<<<dim3(EDIM / 32, M1 / 256), 128>>>(X, AGW, AGB);
    k2_maskT<<<dim3(DDIM / 64, BATCH), 128>>>(X);
    k3_zero<<<3, 256>>>(out);
    k3_contract<<<EDIM, 256>>>(LW, out);
}

// round 7
// speedup vs baseline: 1.5237x; 1.1193x over previous
#include <cuda_runtime.h>
#include <cuda_bf16.h>

// Problem dims (fixed by reference)
#define HWDIM 196
#define BATCH 64
#define DDIM  768
#define EDIM  256
#define CDIM  10
#define M1    (BATCH * HWDIM)   // 12544 rows (b,h)

typedef unsigned long long ull;

// Packed dual-fp32 FMA: acc.{lo,hi} += a.{lo,hi} * b.{lo,hi}
#define FMA2(acc, a, b) \
    asm("fma.rn.f32x2 %0, %1, %2, %0;" : "+l"(acc) : "l"(a), "l"(b))
#define PACK2(p, v) \
    asm("mov.b64 %0, {%1, %1};" : "=l"(p) : "f"(v))
#define UNPACK2(lo, hi, p) \
    asm("mov.b64 {%0, %1}, %2;" : "=f"(lo), "=f"(hi) : "l"(p))

__device__ __forceinline__ void cp16(void* smem_dst, const void* gsrc) {
    unsigned sa = (unsigned)__cvta_generic_to_shared(smem_dst);
    asm volatile("cp.async.cg.shared.global [%0], [%1], 16;" :: "r"(sa), "l"(gsrc));
}
#define CP_COMMIT() asm volatile("cp.async.commit_group;")
#define CP_WAIT0()  asm volatile("cp.async.wait_group 0;")

// Scratch (static device global — no allocation anywhere)
__device__ float g_S[(size_t)M1 * EDIM];            // sign pattern, 12.8 MB

// ---------------------------------------------------------------------------
// Kernel 1: S = (X @ ag_w^T + ag_b) > 0   (M=12544, N=256, K=768, fp32 exact)
// Tile 256(M) x 32(N), 128 threads, micro 16Mx4N via f32x2, BK=16,
// double-buffered smem. grid (8, 49).
// ---------------------------------------------------------------------------
__global__ __launch_bounds__(128) void k1_sign_gemm(
    const float* __restrict__ X, const float* __restrict__ W,
    const float* __restrict__ bias)
{
    __shared__ float Xs[2][16][260];
    __shared__ float Ws[2][16][36];

    const int tid = threadIdx.x;
    const int tx  = tid & 7;      // N dir: 4 cols each
    const int ty  = tid >> 3;     // M dir: 16 rows each (0..15)
    const int m0  = blockIdx.y * 256;
    const int n0  = blockIdx.x * 32;

    const int ar  = tid >> 2;          // 0..31
    const int ac4 = (tid & 3) * 4;     // k sub-offset

    float4 xa[8], wa;

    auto gload = [&](int k0) {
        #pragma unroll
        for (int l = 0; l < 8; l++)
            xa[l] = *reinterpret_cast<const float4*>(
                &X[(size_t)(m0 + ar + l * 32) * DDIM + k0 + ac4]);
        wa = *reinterpret_cast<const float4*>(
            &W[(size_t)(n0 + ar) * DDIM + k0 + ac4]);
    };
    auto sstore = [&](int nb) {
        #pragma unroll
        for (int l = 0; l < 8; l++) {
            Xs[nb][ac4 + 0][ar + l * 32] = xa[l].x;
            Xs[nb][ac4 + 1][ar + l * 32] = xa[l].y;
            Xs[nb][ac4 + 2][ar + l * 32] = xa[l].z;
            Xs[nb][ac4 + 3][ar + l * 32] = xa[l].w;
        }
        Ws[nb][ac4 + 0][ar] = wa.x;
        Ws[nb][ac4 + 1][ar] = wa.y;
        Ws[nb][ac4 + 2][ar] = wa.z;
        Ws[nb][ac4 + 3][ar] = wa.w;
    };

    gload(0);
    sstore(0);
    __syncthreads();

    ull acc2[8][4];
    #pragma unroll
    for (int i = 0; i < 8; i++)
        #pragma unroll
        for (int j = 0; j < 4; j++) acc2[i][j] = 0ull;

    int buf = 0;
    const int NT = DDIM / 16;   // 48
    for (int t = 0; t < NT; t++) {
        if (t < NT - 1) gload((t + 1) * 16);

        #pragma unroll
        for (int kk = 0; kk < 16; kk++) {
            ull ra2[8];
            #pragma unroll
            for (int u = 0; u < 4; u++) {
                ulonglong2 a = *reinterpret_cast<const ulonglong2*>(
                    &Xs[buf][kk][ty * 16 + u * 4]);
                ra2[2 * u + 0] = a.x;
                ra2[2 * u + 1] = a.y;
            }
            float4 wb = *reinterpret_cast<const float4*>(&Ws[buf][kk][tx * 4]);
            ull rb2[4];
            PACK2(rb2[0], wb.x);
            PACK2(rb2[1], wb.y);
            PACK2(rb2[2], wb.z);
            PACK2(rb2[3], wb.w);
            #pragma unroll
            for (int i = 0; i < 8; i++)
                #pragma unroll
                for (int j = 0; j < 4; j++) FMA2(acc2[i][j], ra2[i], rb2[j]);
        }

        if (t < NT - 1) sstore(buf ^ 1);
        buf ^= 1;
        __syncthreads();
    }

    float accf[16][4];
    #pragma unroll
    for (int p = 0; p < 8; p++)
        #pragma unroll
        for (int j = 0; j < 4; j++)
            UNPACK2(accf[2 * p][j], accf[2 * p + 1][j], acc2[p][j]);

    float bv[4];
    #pragma unroll
    for (int j = 0; j < 4; j++) bv[j] = bias[n0 + tx * 4 + j];

    #pragma unroll
    for (int r = 0; r < 16; r++) {
        int m = m0 + ty * 16 + r;
        float4 o;
        o.x = (accf[r][0] + bv[0] > 0.f) ? 1.f : 0.f;
        o.y = (accf[r][1] + bv[1] > 0.f) ? 1.f : 0.f;
        o.z = (accf[r][2] + bv[2] > 0.f) ? 1.f : 0.f;
        o.w = (accf[r][3] + bv[3] > 0.f) ? 1.f : 0.f;
        *reinterpret_cast<float4*>(&g_S[(size_t)m * EDIM + n0 + tx * 4]) = o;
    }
}

// ---------------------------------------------------------------------------
// Kernel 2 (FUSED): per (d-slice, b): compute T-tile [256e x 64d] in regs,
// then contract with lm_w in the epilogue and atomicAdd 10 values into out.
// Eliminates the 50 MB g_T intermediate entirely. grid (12, 64), 128 thr.
// ---------------------------------------------------------------------------
__global__ __launch_bounds__(128) void k2_fused(
    const float* __restrict__ X, const float* __restrict__ LW,
    float* __restrict__ out)
{
    __shared__ float Ss[2][16][260];
    __shared__ float Xs2[2][16][68];

    const int tid = threadIdx.x;
    const int tx  = tid & 7;     // d dir: 8 each
    const int ty  = tid >> 3;    // e dir: 16 each
    const int b   = blockIdx.y;
    const int d0  = blockIdx.x * 64;

    const float* Sb = &g_S[(size_t)b * HWDIM * EDIM];
    const float* Xb = &X[(size_t)b * HWDIM * DDIM];

    auto issue = [&](int k0, int nb) {
        #pragma unroll
        for (int l = 0; l < 8; l++) {
            int s  = tid + l * 128;
            int h  = s >> 6;
            int e4 = (s & 63) * 4;
            int hh = k0 + h;
            if (hh < HWDIM)
                cp16(&Ss[nb][h][e4], &Sb[(size_t)hh * EDIM + e4]);
            else
                *reinterpret_cast<float4*>(&Ss[nb][h][e4]) =
                    make_float4(0.f, 0.f, 0.f, 0.f);
        }
        #pragma unroll
        for (int l = 0; l < 2; l++) {
            int s  = tid + l * 128;
            int h  = s >> 4;
            int d4 = (s & 15) * 4;
            int hh = k0 + h;
            if (hh < HWDIM)
                cp16(&Xs2[nb][h][d4], &Xb[(size_t)hh * DDIM + d0 + d4]);
            else
                *reinterpret_cast<float4*>(&Xs2[nb][h][d4]) =
                    make_float4(0.f, 0.f, 0.f, 0.f);
        }
        CP_COMMIT();
    };

    issue(0, 0);

    ull acc2[8][8];
    #pragma unroll
    for (int i = 0; i < 8; i++)
        #pragma unroll
        for (int j = 0; j < 8; j++) acc2[i][j] = 0ull;

    int buf = 0;
    const int NT = (HWDIM + 15) / 16;   // 13
    for (int t = 0; t < NT; t++) {
        CP_WAIT0();
        __syncthreads();
        if (t < NT - 1) issue((t + 1) * 16, buf ^ 1);

        #pragma unroll
        for (int kk = 0; kk < 16; kk++) {
            ull ra2[8];
            #pragma unroll
            for (int u = 0; u < 4; u++) {
                ulonglong2 a = *reinterpret_cast<const ulonglong2*>(
                    &Ss[buf][kk][ty * 16 + u * 4]);
                ra2[2 * u + 0] = a.x;
                ra2[2 * u + 1] = a.y;
            }
            float rbv[8];
            *reinterpret_cast<float4*>(&rbv[0]) =
                *reinterpret_cast<const float4*>(&Xs2[buf][kk][tx * 8 + 0]);
            *reinterpret_cast<float4*>(&rbv[4]) =
                *reinterpret_cast<const float4*>(&Xs2[buf][kk][tx * 8 + 4]);
            ull rb2[8];
            #pragma unroll
            for (int j = 0; j < 8; j++) PACK2(rb2[j], rbv[j]);
            #pragma unroll
            for (int i = 0; i < 8; i++)
                #pragma unroll
                for (int j = 0; j < 8; j++) FMA2(acc2[i][j], ra2[i], rb2[j]);
        }
        buf ^= 1;
    }

    // ---- fused epilogue: partial[c] = sum over this thread's (e,d) of
    //      T[e][d] * LW[e*CDIM+c][d];  thread covers e = ty*16+2i{,+1},
    //      d = d0 + tx*8 + j (j=0..7).
    float partial[CDIM];
    #pragma unroll
    for (int c = 0; c < CDIM; c++) partial[c] = 0.f;

    #pragma unroll
    for (int i = 0; i < 8; i++) {
        float elo[8], ehi[8];
        #pragma unroll
        for (int j = 0; j < 8; j++) UNPACK2(elo[j], ehi[j], acc2[i][j]);
        const int e0 = ty * 16 + 2 * i;
        #pragma unroll
        for (int c = 0; c < CDIM; c++) {
            const float* r0 = &LW[((size_t)e0 * CDIM + c) * DDIM + d0 + tx * 8];
            const float* r1 = &LW[((size_t)(e0 + 1) * CDIM + c) * DDIM + d0 + tx * 8];
            float4 a0 = *reinterpret_cast<const float4*>(r0 + 0);
            float4 a1 = *reinterpret_cast<const float4*>(r0 + 4);
            float4 b0 = *reinterpret_cast<const float4*>(r1 + 0);
            float4 b1 = *reinterpret_cast<const float4*>(r1 + 4);
            float s = 0.f;
            s += elo[0] * a0.x + elo[1] * a0.y + elo[2] * a0.z + elo[3] * a0.w;
            s += elo[4] * a1.x + elo[5] * a1.y + elo[6] * a1.z + elo[7] * a1.w;
            s += ehi[0] * b0.x + ehi[1] * b0.y + ehi[2] * b0.z + ehi[3] * b0.w;
            s += ehi[4] * b1.x + ehi[5] * b1.y + ehi[6] * b1.z + ehi[7] * b1.w;
            partial[c] += s;
        }
    }

    // ---- block reduction over 128 threads (reuse Ss as scratch)
    float* red = &Ss[0][0][0];    // need 10*128 = 1280 floats; Ss has 8320
    __syncthreads();              // everyone done reading smem tiles
    #pragma unroll
    for (int c = 0; c < CDIM; c++) red[c * 128 + tid] = partial[c];
    __syncthreads();

    #pragma unroll
    for (int off = 64; off >= 1; off >>= 1) {
        if (tid < off) {
            #pragma unroll
            for (int c = 0; c < CDIM; c++)
                red[c * 128 + tid] += red[c * 128 + tid + off];
        }
        __syncthreads();
    }

    const float scale = 1.0f / ((float)HWDIM * (float)EDIM);
    if (tid < CDIM)
        atomicAdd(&out[b * CDIM + tid], red[tid * 128] * scale);
}

// ---------------------------------------------------------------------------
// Zero the output (harness poisons it; atomics accumulate into it).
// ---------------------------------------------------------------------------
__global__ void k_zero(float* __restrict__ out)
{
    int p = blockIdx.x * blockDim.x + threadIdx.x;
    if (p < BATCH * CDIM) out[p] = 0.f;
}

// ---------------------------------------------------------------------------
extern "C" void kernel_launch(void* const* d_in, const int* in_sizes, int n_in,
                              void* d_out, int out_size)
{
    const float* X   = (const float*)d_in[0];   // (64,196,768)
    const float* AGW = (const float*)d_in[1];   // (256,768)
    const float* AGB = (const float*)d_in[2];   // (256,)
    const float* LW  = (const float*)d_in[3];   // (2560,768)
    float* out = (float*)d_out;                 // (64,10)

    k1_sign_gemm<<<dim3(EDIM / 32, M1 / 256), 128>>>(X, AGW, AGB);
    k_zero<<<3, 256>>>(out);
    k2_fused<<<dim3(DDIM / 64, BATCH), 128>>>(X, LW, out);
}